// round 2
// baseline (speedup 1.0000x reference)
#include <cuda_runtime.h>

#define P       12
#define H       128
#define DIN     32
#define NB      16          // batch graphs per block
#define THREADS 256

// SMEM layout (floats):
//   sW   : [0, 16384)                 one GCN layer's weights (also holds W_in + x tile in phase 0, G/O1/Wout1 in head)
//   sH   : [16384, 16384+NB*P*H)      node features for NB graphs
//   sA   : next NB*P*P                normalized adjacency
//   sD   : next NB*P                  d^{-1/2}
#define SW_OFF   0
#define SH_OFF   16384
#define SA_OFF   (SH_OFF + NB*P*H)          // 16384 + 24576 = 40960
#define SD_OFF   (SA_OFF + NB*P*P)          // 40960 + 2304  = 43264
#define SMEM_FLOATS (SD_OFF + NB*P)         // 43456
#define SMEM_BYTES  (SMEM_FLOATS * 4)       // 173824 B

extern __shared__ float smem[];

__global__ __launch_bounds__(THREADS, 1)
void gnn_fused_kernel(const float* __restrict__ x,
                      const float* __restrict__ W_in,
                      const float* __restrict__ b_in,
                      const float* __restrict__ W_gcn,
                      const float* __restrict__ b_gcn,
                      const float* __restrict__ W_out1,
                      const float* __restrict__ b_out1,
                      const float* __restrict__ W_out2,
                      const float* __restrict__ b_out2,
                      float* __restrict__ out,
                      int B)
{
    float* sW = smem + SW_OFF;
    float* sH = smem + SH_OFF;
    float* sA = smem + SA_OFF;
    float* sD = smem + SD_OFF;

    const int tid  = threadIdx.x;
    const int half = tid >> 7;       // 0 or 1: which of the 2 concurrent graphs
    const int j    = tid & 127;      // output column
    const long b0  = (long)blockIdx.x * NB;
    const int  nb  = (B - b0 < NB) ? (int)(B - b0) : NB;

    // ---------------- Phase 0: stage W_in (4096 f) + x tile (nb*384 f) ----------------
    float* sWin = sW;                // [DIN][H]
    float* sX   = sW + DIN * H;      // [NB][P][DIN]
    for (int i = tid; i < DIN * H; i += THREADS) sWin[i] = W_in[i];
    {
        const float* xg = x + b0 * (P * DIN);
        for (int i = tid; i < nb * P * DIN; i += THREADS) sX[i] = xg[i];
    }
    __syncthreads();

    // ---------------- Adjacency: rows + degree^{-1/2} ----------------
    if (tid < nb * P) {
        const int bb = tid / P, p = tid - bb * P;
        const float lp = sX[bb * P * DIN + p * DIN];
        float deg = 0.f;
        float row[P];
        #pragma unroll
        for (int q = 0; q < P; q++) {
            float lq   = sX[bb * P * DIN + q * DIN];
            float d    = fmodf(fabsf(lp - lq), 360.0f);
            float dist = fminf(d, 360.0f - d);
            float a    = (dist < 10.0f) ? 1.0f : 0.0f;   // diag: dist=0 -> 1
            if (q == p) a += 1.0f;                       // + eye (add_self_loops)
            row[q] = a;
            deg   += a;
        }
        #pragma unroll
        for (int q = 0; q < P; q++) sA[(bb * P + p) * P + q] = row[q];
        sD[tid] = rsqrtf(fmaxf(deg, 1e-12f));
    }
    __syncthreads();
    if (tid < nb * P) {      // normalize: Ahat = D^-1/2 (A+I) D^-1/2
        const int bb = tid / P, p = tid - bb * P;
        const float dp = sD[tid];
        #pragma unroll
        for (int q = 0; q < P; q++)
            sA[(bb * P + p) * P + q] *= dp * sD[bb * P + q];
    }

    // ---------------- Input projection: h0 = x @ W_in + b_in (no relu) ----------------
    {
        const float bj = b_in[j];
        for (int bb = half; bb < nb; bb += 2) {
            float acc[P];
            #pragma unroll
            for (int p = 0; p < P; p++) acc[p] = bj;
            const float* xr = sX + bb * P * DIN;
            #pragma unroll
            for (int k4 = 0; k4 < DIN; k4 += 4) {
                const float w0 = sWin[(k4 + 0) * H + j];
                const float w1 = sWin[(k4 + 1) * H + j];
                const float w2 = sWin[(k4 + 2) * H + j];
                const float w3 = sWin[(k4 + 3) * H + j];
                #pragma unroll
                for (int p = 0; p < P; p++) {
                    const float4 xv = *(const float4*)&xr[p * DIN + k4];
                    acc[p] = fmaf(xv.x, w0, acc[p]);
                    acc[p] = fmaf(xv.y, w1, acc[p]);
                    acc[p] = fmaf(xv.z, w2, acc[p]);
                    acc[p] = fmaf(xv.w, w3, acc[p]);
                }
            }
            #pragma unroll
            for (int p = 0; p < P; p++) sH[(bb * P + p) * H + j] = acc[p];
        }
    }

    // ---------------- 3 GCN layers: h = relu(Ahat @ (h @ W_l) + b_l) ----------------
    for (int l = 0; l < 3; l++) {
        __syncthreads();                         // all reads of sW/sH of prev phase done
        const float* Wg = W_gcn + l * H * H;
        for (int i = tid * 4; i < H * H; i += THREADS * 4)
            *(float4*)&sW[i] = *(const float4*)&Wg[i];
        const float bg = b_gcn[l * H + j];
        __syncthreads();

        for (int bb = half; bb < nb; bb += 2) {
            float acc[P];
            #pragma unroll
            for (int p = 0; p < P; p++) acc[p] = 0.f;
            const float* hr = sH + bb * P * H;
            #pragma unroll 4
            for (int k4 = 0; k4 < H; k4 += 4) {
                const float w0 = sW[(k4 + 0) * H + j];
                const float w1 = sW[(k4 + 1) * H + j];
                const float w2 = sW[(k4 + 2) * H + j];
                const float w3 = sW[(k4 + 3) * H + j];
                #pragma unroll
                for (int p = 0; p < P; p++) {
                    const float4 hv = *(const float4*)&hr[p * H + k4];
                    acc[p] = fmaf(hv.x, w0, acc[p]);
                    acc[p] = fmaf(hv.y, w1, acc[p]);
                    acc[p] = fmaf(hv.z, w2, acc[p]);
                    acc[p] = fmaf(hv.w, w3, acc[p]);
                }
            }
            __syncthreads();                     // reads of sH[bb] done before overwrite
            const float* Ar = sA + bb * P * P;
            #pragma unroll
            for (int p = 0; p < P; p++) {
                float s = bg;
                #pragma unroll
                for (int q = 0; q < P; q++) s = fmaf(Ar[p * P + q], acc[q], s);
                sH[(bb * P + p) * H + j] = fmaxf(s, 0.f);
            }
        }
    }

    // ---------------- Head: mean-pool -> 64 (relu) -> 3 ----------------
    __syncthreads();
    float* sG     = sW;                 // [NB][H]
    float* sO1    = sW + NB * H;        // [NB][64]
    float* sWout1 = sW + NB * H + NB * 64;   // [H][64] = 8192 floats (fits: 3072+8192 < 16384)
    for (int i = tid; i < H * 64; i += THREADS) sWout1[i] = W_out1[i];
    for (int bb = half; bb < nb; bb += 2) {
        float s = 0.f;
        #pragma unroll
        for (int p = 0; p < P; p++) s += sH[(bb * P + p) * H + j];
        sG[bb * H + j] = s * (1.0f / 12.0f);
    }
    __syncthreads();
    for (int i = tid; i < nb * 64; i += THREADS) {
        const int bb = i >> 6, m = i & 63;
        float s = b_out1[m];
        const float* gr = sG + bb * H;
        #pragma unroll 8
        for (int k = 0; k < H; k++) s = fmaf(gr[k], sWout1[k * 64 + m], s);
        sO1[i] = fmaxf(s, 0.f);
    }
    __syncthreads();
    for (int i = tid; i < nb * 3; i += THREADS) {
        const int bb = i / 3, d = i - bb * 3;
        float s = b_out2[d];
        const float* o = sO1 + bb * 64;
        #pragma unroll
        for (int m = 0; m < 64; m++) s = fmaf(o[m], W_out2[m * 3 + d], s);
        out[(b0 + bb) * 3 + d] = s;
    }
}

extern "C" void kernel_launch(void* const* d_in, const int* in_sizes, int n_in,
                              void* d_out, int out_size)
{
    const float* x      = (const float*)d_in[0];
    const float* W_in   = (const float*)d_in[1];
    const float* b_in   = (const float*)d_in[2];
    const float* W_gcn  = (const float*)d_in[3];
    const float* b_gcn  = (const float*)d_in[4];
    const float* W_out1 = (const float*)d_in[5];
    const float* b_out1 = (const float*)d_in[6];
    const float* W_out2 = (const float*)d_in[7];
    const float* b_out2 = (const float*)d_in[8];
    float* out = (float*)d_out;

    const int B = in_sizes[0] / (P * DIN);
    const int blocks = (B + NB - 1) / NB;

    cudaFuncSetAttribute(gnn_fused_kernel,
                         cudaFuncAttributeMaxDynamicSharedMemorySize, SMEM_BYTES);
    gnn_fused_kernel<<<blocks, THREADS, SMEM_BYTES>>>(
        x, W_in, b_in, W_gcn, b_gcn, W_out1, b_out1, W_out2, b_out2, out, B);
}

// round 3
// speedup vs baseline: 1.1107x; 1.1107x over previous
#include <cuda_runtime.h>

#define P       12
#define H       128
#define DIN     32
#define NB      16          // batch graphs per block
#define THREADS 512         // 4 quads x 128 columns

// SMEM layout (floats):
#define SW_OFF   0                           // 16384 floats: packed weights / staging / head scratch
#define SH_OFF   16384                       // NB*P*H = 24576 floats
#define SA_OFF   (SH_OFF + NB*P*H)           // 40960: NB*P*P = 2304
#define SD_OFF   (SA_OFF + NB*P*P)           // 43264: NB*P
#define SMEM_FLOATS (SD_OFF + NB*P)          // 43456
#define SMEM_BYTES  (SMEM_FLOATS * 4)        // 173824 B

extern __shared__ float smem[];

__device__ __forceinline__ void ffma2(unsigned long long& d,
                                      unsigned long long a,
                                      unsigned long long b) {
    asm volatile("fma.rn.f32x2 %0, %1, %2, %0;" : "+l"(d) : "l"(a), "l"(b));
}
__device__ __forceinline__ unsigned long long pack2(float x, float y) {
    unsigned long long r;
    asm("mov.b64 %0, {%1, %2};" : "=l"(r) : "f"(x), "f"(y));
    return r;
}
__device__ __forceinline__ float2 unpack2(unsigned long long v) {
    float2 f;
    asm("mov.b64 {%0, %1}, %2;" : "=f"(f.x), "=f"(f.y) : "l"(v));
    return f;
}

__global__ __launch_bounds__(THREADS, 1)
void gnn_fused_kernel(const float* __restrict__ x,
                      const float* __restrict__ W_in,
                      const float* __restrict__ b_in,
                      const float* __restrict__ W_gcn,
                      const float* __restrict__ b_gcn,
                      const float* __restrict__ W_out1,
                      const float* __restrict__ b_out1,
                      const float* __restrict__ W_out2,
                      const float* __restrict__ b_out2,
                      float* __restrict__ out,
                      int B)
{
    float* sW = smem + SW_OFF;
    float* sH = smem + SH_OFF;
    float* sA = smem + SA_OFF;
    float* sD = smem + SD_OFF;

    const int tid  = threadIdx.x;
    const int quad = tid >> 7;        // 0..3: which quarter of graphs
    const int j    = tid & 127;       // output column
    const long b0  = (long)blockIdx.x * NB;
    const int  nb  = (B - b0 < NB) ? (int)(B - b0) : NB;

    // ---------------- Phase 0: stage packed W_in + x tile ----------------
    float2* sWin = (float2*)sW;              // [DIN/2][H] pairs {W[2k][j], W[2k+1][j]}
    float*  sX   = sW + DIN * H;             // [NB][P][DIN]
    for (int i = tid; i < (DIN / 2) * H; i += THREADS) {
        const int k2 = i >> 7, jj = i & 127;
        sWin[i] = make_float2(W_in[(2 * k2) * H + jj], W_in[(2 * k2 + 1) * H + jj]);
    }
    {
        const float* xg = x + b0 * (P * DIN);
        for (int i = tid; i < nb * P * DIN; i += THREADS) sX[i] = xg[i];
    }
    __syncthreads();

    // ---------------- Adjacency (symmetric) + degree^{-1/2} ----------------
    if (tid < nb * P) {
        const int bb = tid / P, p = tid - bb * P;
        const float lp = sX[bb * P * DIN + p * DIN];
        float deg = 0.f;
        float row[P];
        #pragma unroll
        for (int q = 0; q < P; q++) {
            float lq   = sX[bb * P * DIN + q * DIN];
            float d    = fmodf(fabsf(lp - lq), 360.0f);
            float dist = fminf(d, 360.0f - d);
            float a    = (dist < 10.0f) ? 1.0f : 0.0f;   // diag: dist=0 -> 1
            if (q == p) a += 1.0f;                       // + eye (add_self_loops)
            row[q] = a;
            deg   += a;
        }
        #pragma unroll
        for (int q = 0; q < P; q++) sA[(bb * P + p) * P + q] = row[q];
        sD[tid] = rsqrtf(fmaxf(deg, 1e-12f));
    }
    __syncthreads();
    if (tid < nb * P) {      // Ahat = D^-1/2 (A+I) D^-1/2  (stays symmetric)
        const int bb = tid / P, p = tid - bb * P;
        const float dp = sD[tid];
        #pragma unroll
        for (int q = 0; q < P; q++)
            sA[(bb * P + p) * P + q] *= dp * sD[bb * P + q];
    }

    // ---------------- Input projection: h0 = x @ W_in + b_in ----------------
    {
        const float bj = b_in[j];
        const unsigned long long* wp = (const unsigned long long*)sWin;
        for (int bb = quad; bb < nb; bb += 4) {
            unsigned long long acc[P];
            #pragma unroll
            for (int p = 0; p < P; p++) acc[p] = pack2(bj, 0.f);
            const float* xr = sX + bb * P * DIN;
            #pragma unroll
            for (int k4 = 0; k4 < DIN; k4 += 4) {
                const unsigned long long w0 = wp[(k4 / 2) * H + j];
                const unsigned long long w1 = wp[(k4 / 2 + 1) * H + j];
                #pragma unroll
                for (int p = 0; p < P; p++) {
                    const ulonglong2 hv = *(const ulonglong2*)&xr[p * DIN + k4];
                    ffma2(acc[p], hv.x, w0);
                    ffma2(acc[p], hv.y, w1);
                }
            }
            #pragma unroll
            for (int p = 0; p < P; p++) {
                const float2 a = unpack2(acc[p]);
                sH[(bb * P + p) * H + j] = a.x + a.y;
            }
        }
    }

    // ---------------- 3 GCN layers: h = relu(Ahat @ (h @ W_l) + b_l) ----------------
    for (int l = 0; l < 3; l++) {
        __syncthreads();                 // prior phase's reads of sW / writes of sH done
        const float* Wg = W_gcn + l * H * H;
        float2* sWp = (float2*)sW;       // [H/2][H] pairs {W[2k][j], W[2k+1][j]}
        for (int i = tid; i < (H / 2) * H; i += THREADS) {
            const int k2 = i >> 7, jj = i & 127;
            sWp[i] = make_float2(Wg[(2 * k2) * H + jj], Wg[(2 * k2 + 1) * H + jj]);
        }
        const float bg = b_gcn[l * H + j];
        __syncthreads();

        const unsigned long long* wp = (const unsigned long long*)sWp;
        for (int it = 0; it < NB / 4; it++) {
            const int bb = quad + 4 * it;

            unsigned long long acc[P];
            #pragma unroll
            for (int p = 0; p < P; p++) acc[p] = 0ull;
            const float* hr = sH + bb * P * H;
            #pragma unroll 4
            for (int k4 = 0; k4 < H; k4 += 4) {
                const unsigned long long w0 = wp[(k4 / 2) * H + j];
                const unsigned long long w1 = wp[(k4 / 2 + 1) * H + j];
                #pragma unroll
                for (int p = 0; p < P; p++) {
                    const ulonglong2 hv = *(const ulonglong2*)&hr[p * H + k4];
                    ffma2(acc[p], hv.x, w0);
                    ffma2(acc[p], hv.y, w1);
                }
            }
            __syncthreads();             // all reads of sH done before overwrite

            // reduce even/odd partial sums, then Ahat mix (symmetric A, FFMA2 over p-pairs)
            float av[P];
            #pragma unroll
            for (int p = 0; p < P; p++) { const float2 a = unpack2(acc[p]); av[p] = a.x + a.y; }

            const float* Ar = sA + bb * P * P;
            unsigned long long s2[P / 2];
            #pragma unroll
            for (int h2 = 0; h2 < P / 2; h2++) s2[h2] = pack2(bg, bg);
            #pragma unroll
            for (int q = 0; q < P; q++) {
                const unsigned long long aq = pack2(av[q], av[q]);
                const unsigned long long* arp = (const unsigned long long*)&Ar[q * P];
                #pragma unroll
                for (int h2 = 0; h2 < P / 2; h2++) ffma2(s2[h2], arp[h2], aq);
            }
            #pragma unroll
            for (int h2 = 0; h2 < P / 2; h2++) {
                const float2 sv = unpack2(s2[h2]);
                sH[(bb * P + 2 * h2)     * H + j] = fmaxf(sv.x, 0.f);
                sH[(bb * P + 2 * h2 + 1) * H + j] = fmaxf(sv.y, 0.f);
            }
        }
    }

    // ---------------- Head: mean-pool -> 64 (relu) -> 3 ----------------
    __syncthreads();
    float* sG   = sW;                     // [NB][H]
    float* sO1  = sW + NB * H;            // [NB][64]
    float* sWo1 = sW + NB * H + NB * 64;  // [H][64]
    for (int i = tid; i < H * 64; i += THREADS) sWo1[i] = W_out1[i];
    for (int bb = quad; bb < nb; bb += 4) {
        float s = 0.f;
        #pragma unroll
        for (int p = 0; p < P; p++) s += sH[(bb * P + p) * H + j];
        sG[bb * H + j] = s * (1.0f / 12.0f);
    }
    __syncthreads();
    for (int i = tid; i < nb * 64; i += THREADS) {
        const int bb = i >> 6, m = i & 63;
        float s = b_out1[m];
        const float* gr = sG + bb * H;
        #pragma unroll 8
        for (int k = 0; k < H; k++) s = fmaf(gr[k], sWo1[k * 64 + m], s);
        sO1[i] = fmaxf(s, 0.f);
    }
    __syncthreads();
    for (int i = tid; i < nb * 3; i += THREADS) {
        const int bb = i / 3, d = i - bb * 3;
        float s = b_out2[d];
        const float* o = sO1 + bb * 64;
        #pragma unroll
        for (int m = 0; m < 64; m++) s = fmaf(o[m], W_out2[m * 3 + d], s);
        out[(b0 + bb) * 3 + d] = s;
    }
}

extern "C" void kernel_launch(void* const* d_in, const int* in_sizes, int n_in,
                              void* d_out, int out_size)
{
    const float* x      = (const float*)d_in[0];
    const float* W_in   = (const float*)d_in[1];
    const float* b_in   = (const float*)d_in[2];
    const float* W_gcn  = (const float*)d_in[3];
    const float* b_gcn  = (const float*)d_in[4];
    const float* W_out1 = (const float*)d_in[5];
    const float* b_out1 = (const float*)d_in[6];
    const float* W_out2 = (const float*)d_in[7];
    const float* b_out2 = (const float*)d_in[8];
    float* out = (float*)d_out;

    const int B = in_sizes[0] / (P * DIN);
    const int blocks = (B + NB - 1) / NB;

    cudaFuncSetAttribute(gnn_fused_kernel,
                         cudaFuncAttributeMaxDynamicSharedMemorySize, SMEM_BYTES);
    gnn_fused_kernel<<<blocks, THREADS, SMEM_BYTES>>>(
        x, W_in, b_in, W_gcn, b_gcn, W_out1, b_out1, W_out2, b_out2, out, B);
}

// round 4
// speedup vs baseline: 1.6399x; 1.4764x over previous
#include <cuda_runtime.h>

#define P       12
#define H       128
#define DIN     32
#define NB      16
#define THREADS 256
#define WARPS   8

typedef unsigned long long ull;

// SMEM layout (float units):
//  sW  [0, 16384)        : weight pairs ull[64][128] for GCN layers; W_in pairs + x tile in phase 0; head scratch
//  sH  [16384, 40960)    : node features [NB][P][H]
//  sA2 [40960, 45568)    : adjacency ull[NB][P][P], each entry duplicated {a,a}
//  sD  [45568, 45760)    : deg^{-1/2}
#define SW_OFF  0
#define SX_OFF  4096                      // x tile inside sW region (after W_in pairs: 2048 ull = 4096 f)
#define SH_OFF  16384
#define SA_OFF  (SH_OFF + NB*P*H)         // 40960
#define SD_OFF  (SA_OFF + 2*NB*P*P)       // 45568
#define SMEM_FLOATS (SD_OFF + NB*P)       // 45760
#define SMEM_BYTES  (SMEM_FLOATS * 4)     // 183040 B

extern __shared__ float smem[];

__device__ __forceinline__ void ffma2(ull& d, ull a, ull b) {
    asm volatile("fma.rn.f32x2 %0, %1, %2, %0;" : "+l"(d) : "l"(a), "l"(b));
}
__device__ __forceinline__ ull pack2(float x, float y) {
    ull r; asm("mov.b64 %0, {%1, %2};" : "=l"(r) : "f"(x), "f"(y)); return r;
}
__device__ __forceinline__ float2 unpack2(ull v) {
    float2 f; asm("mov.b64 {%0, %1}, %2;" : "=f"(f.x), "=f"(f.y) : "l"(v)); return f;
}

__global__ __launch_bounds__(THREADS, 1)
void gnn_fused_kernel(const float* __restrict__ x,
                      const float* __restrict__ W_in,
                      const float* __restrict__ b_in,
                      const float* __restrict__ W_gcn,
                      const float* __restrict__ b_gcn,
                      const float* __restrict__ W_out1,
                      const float* __restrict__ b_out1,
                      const float* __restrict__ W_out2,
                      const float* __restrict__ b_out2,
                      float* __restrict__ out,
                      int B)
{
    float* sW  = smem + SW_OFF;
    float* sX  = smem + SX_OFF;
    float* sH  = smem + SH_OFF;
    ull*   sA2 = (ull*)(smem + SA_OFF);
    float* sD  = smem + SD_OFF;

    const int tid  = threadIdx.x;
    const int wid  = tid >> 5;
    const int lane = tid & 31;
    const long b0  = (long)blockIdx.x * NB;
    const int  nb  = (B - b0 < NB) ? (int)(B - b0) : NB;

    const int c0 = lane, c1 = lane + 32, c2 = lane + 64, c3 = lane + 96;

    // ---------------- Phase 0: stage W_in pairs + x tile ----------------
    {
        ull* sWinp = (ull*)sW;                       // [DIN/2][H]
        for (int i = tid; i < (DIN / 2) * H; i += THREADS) {
            const int k2 = i >> 7, j = i & 127;
            sWinp[i] = pack2(W_in[(2 * k2) * H + j], W_in[(2 * k2 + 1) * H + j]);
        }
        const float* xg = x + b0 * (P * DIN);
        for (int i = tid; i < nb * P * DIN; i += THREADS) sX[i] = xg[i];
    }
    __syncthreads();

    // ---------------- Adjacency ----------------
    float arow[P];
    if (tid < nb * P) {
        const int bb = tid / P, p = tid - bb * P;
        const float lp = sX[bb * P * DIN + p * DIN];
        float deg = 0.f;
        #pragma unroll
        for (int q = 0; q < P; q++) {
            float lq   = sX[bb * P * DIN + q * DIN];
            float d    = fmodf(fabsf(lp - lq), 360.0f);
            float dist = fminf(d, 360.0f - d);
            float a    = (dist < 10.0f) ? 1.0f : 0.0f;
            if (q == p) a += 1.0f;
            arow[q] = a;
            deg    += a;
        }
        sD[tid] = rsqrtf(fmaxf(deg, 1e-12f));
    }
    __syncthreads();
    if (tid < nb * P) {
        const int bb = tid / P, p = tid - bb * P;
        const float dp = sD[tid];
        #pragma unroll
        for (int q = 0; q < P; q++) {
            const float a = arow[q] * dp * sD[bb * P + q];
            sA2[(bb * P + p) * P + q] = pack2(a, a);
        }
    }
    // (barrier before first use of sA2 is the layer-0 staging barrier below)

    // ---------------- Input projection: h0 = x @ W_in + b_in ----------------
    {
        const float bj0 = b_in[c0], bj1 = b_in[c1], bj2 = b_in[c2], bj3 = b_in[c3];
        const ull* wp = (const ull*)sW;
        for (int g = wid; g < nb; g += WARPS) {
            ull acc[P][4];
            #pragma unroll
            for (int p = 0; p < P; p++) { acc[p][0]=0; acc[p][1]=0; acc[p][2]=0; acc[p][3]=0; }
            const float* xr = sX + g * P * DIN;
            #pragma unroll 1
            for (int k4 = 0; k4 < DIN; k4 += 4) {
                const int k2 = k4 >> 1;
                const ull wA0 = wp[k2 * H + c0],       wA1 = wp[k2 * H + c1];
                const ull wA2 = wp[k2 * H + c2],       wA3 = wp[k2 * H + c3];
                const ull wB0 = wp[(k2 + 1) * H + c0], wB1 = wp[(k2 + 1) * H + c1];
                const ull wB2 = wp[(k2 + 1) * H + c2], wB3 = wp[(k2 + 1) * H + c3];
                #pragma unroll
                for (int p = 0; p < P; p++) {
                    const ulonglong2 hv = *(const ulonglong2*)&xr[p * DIN + k4];
                    ffma2(acc[p][0], hv.x, wA0); ffma2(acc[p][0], hv.y, wB0);
                    ffma2(acc[p][1], hv.x, wA1); ffma2(acc[p][1], hv.y, wB1);
                    ffma2(acc[p][2], hv.x, wA2); ffma2(acc[p][2], hv.y, wB2);
                    ffma2(acc[p][3], hv.x, wA3); ffma2(acc[p][3], hv.y, wB3);
                }
            }
            float* hw = sH + g * P * H;
            #pragma unroll
            for (int p = 0; p < P; p++) {
                const float2 a0 = unpack2(acc[p][0]), a1 = unpack2(acc[p][1]);
                const float2 a2 = unpack2(acc[p][2]), a3 = unpack2(acc[p][3]);
                hw[p * H + c0] = a0.x + a0.y + bj0;
                hw[p * H + c1] = a1.x + a1.y + bj1;
                hw[p * H + c2] = a2.x + a2.y + bj2;
                hw[p * H + c3] = a3.x + a3.y + bj3;
            }
        }
    }

    // ---------------- 3 GCN layers ----------------
    for (int l = 0; l < 3; l++) {
        __syncthreads();                      // prior phase done with sW (and sA2 written)
        const float* Wg = W_gcn + l * H * H;
        ull* sWp = (ull*)sW;                  // [H/2][H]
        for (int i = tid; i < (H / 2) * H; i += THREADS) {
            const int k2 = i >> 7, j = i & 127;
            sWp[i] = pack2(Wg[(2 * k2) * H + j], Wg[(2 * k2 + 1) * H + j]);
        }
        const ull bg01 = pack2(b_gcn[l * H + c0], b_gcn[l * H + c1]);
        const ull bg23 = pack2(b_gcn[l * H + c2], b_gcn[l * H + c3]);
        __syncthreads();

        const ull* wp = (const ull*)sWp;
        for (int g = wid; g < nb; g += WARPS) {
            // ---- z = h @ W  (per-thread: 12 rows x 4 cols) ----
            ull acc[P][4];
            #pragma unroll
            for (int p = 0; p < P; p++) { acc[p][0]=0; acc[p][1]=0; acc[p][2]=0; acc[p][3]=0; }
            const float* hr = sH + g * P * H;
            #pragma unroll 1
            for (int k4 = 0; k4 < H; k4 += 4) {
                const int k2 = k4 >> 1;
                const ull wA0 = wp[k2 * H + c0],       wA1 = wp[k2 * H + c1];
                const ull wA2 = wp[k2 * H + c2],       wA3 = wp[k2 * H + c3];
                const ull wB0 = wp[(k2 + 1) * H + c0], wB1 = wp[(k2 + 1) * H + c1];
                const ull wB2 = wp[(k2 + 1) * H + c2], wB3 = wp[(k2 + 1) * H + c3];
                #pragma unroll
                for (int p = 0; p < P; p++) {
                    const ulonglong2 hv = *(const ulonglong2*)&hr[p * H + k4];
                    ffma2(acc[p][0], hv.x, wA0); ffma2(acc[p][0], hv.y, wB0);
                    ffma2(acc[p][1], hv.x, wA1); ffma2(acc[p][1], hv.y, wB1);
                    ffma2(acc[p][2], hv.x, wA2); ffma2(acc[p][2], hv.y, wB2);
                    ffma2(acc[p][3], hv.x, wA3); ffma2(acc[p][3], hv.y, wB3);
                }
            }
            // reduce k-parity, repack as col pairs
            ull zp[P][2];
            #pragma unroll
            for (int p = 0; p < P; p++) {
                const float2 a0 = unpack2(acc[p][0]), a1 = unpack2(acc[p][1]);
                const float2 a2 = unpack2(acc[p][2]), a3 = unpack2(acc[p][3]);
                zp[p][0] = pack2(a0.x + a0.y, a1.x + a1.y);
                zp[p][1] = pack2(a2.x + a2.y, a3.x + a3.y);
            }
            // ---- Ahat mix (FFMA2 over col pairs, A broadcast from SMEM) ----
            const ull* Ag = sA2 + g * P * P;
            ull o[P][2];
            #pragma unroll
            for (int p = 0; p < P; p++) { o[p][0] = bg01; o[p][1] = bg23; }
            #pragma unroll
            for (int q = 0; q < P; q++) {
                const ull z0 = zp[q][0], z1 = zp[q][1];
                #pragma unroll
                for (int p = 0; p < P; p++) {
                    const ull a2v = Ag[p * P + q];
                    ffma2(o[p][0], a2v, z0);
                    ffma2(o[p][1], a2v, z1);
                }
            }
            // ---- relu + store (own graph only: no barrier needed) ----
            float* hw = sH + g * P * H;
            #pragma unroll
            for (int p = 0; p < P; p++) {
                const float2 v0 = unpack2(o[p][0]), v1 = unpack2(o[p][1]);
                hw[p * H + c0] = fmaxf(v0.x, 0.f);
                hw[p * H + c1] = fmaxf(v0.y, 0.f);
                hw[p * H + c2] = fmaxf(v1.x, 0.f);
                hw[p * H + c3] = fmaxf(v1.y, 0.f);
            }
        }
    }

    // ---------------- Head: mean-pool -> 64 (relu) -> 3 ----------------
    __syncthreads();                          // all warps done reading last layer's sW
    float* sG   = sW;                         // [NB][H]
    float* sO1  = sW + NB * H;                // [NB][64]
    ull*   sWo1 = (ull*)(sW + NB * H + NB * 64);   // [64][64] pairs over k
    for (int i = tid; i < (H / 2) * 64; i += THREADS) {
        const int k2 = i >> 6, m = i & 63;
        sWo1[i] = pack2(W_out1[(2 * k2) * 64 + m], W_out1[(2 * k2 + 1) * 64 + m]);
    }
    for (int g = wid; g < nb; g += WARPS) {
        float s0 = 0.f, s1 = 0.f, s2 = 0.f, s3 = 0.f;
        const float* hr = sH + g * P * H;
        #pragma unroll
        for (int p = 0; p < P; p++) {
            s0 += hr[p * H + c0]; s1 += hr[p * H + c1];
            s2 += hr[p * H + c2]; s3 += hr[p * H + c3];
        }
        sG[g * H + c0] = s0 * (1.0f / 12.0f);
        sG[g * H + c1] = s1 * (1.0f / 12.0f);
        sG[g * H + c2] = s2 * (1.0f / 12.0f);
        sG[g * H + c3] = s3 * (1.0f / 12.0f);
    }
    __syncthreads();
    for (int i = tid; i < nb * 64; i += THREADS) {
        const int bb = i >> 6, m = i & 63;
        ull acc2 = pack2(b_out1[m], 0.f);
        const ull* gr = (const ull*)(sG + bb * H);
        #pragma unroll 8
        for (int k2 = 0; k2 < H / 2; k2++)
            ffma2(acc2, gr[k2], sWo1[k2 * 64 + m]);
        const float2 a = unpack2(acc2);
        sO1[i] = fmaxf(a.x + a.y, 0.f);
    }
    __syncthreads();
    if (tid < nb * 3) {
        const int bb = tid / 3, d = tid - bb * 3;
        float s = b_out2[d];
        const float* o1 = sO1 + bb * 64;
        #pragma unroll
        for (int m = 0; m < 64; m++) s = fmaf(o1[m], W_out2[m * 3 + d], s);
        out[(b0 + bb) * 3 + d] = s;
    }
}

extern "C" void kernel_launch(void* const* d_in, const int* in_sizes, int n_in,
                              void* d_out, int out_size)
{
    const float* x      = (const float*)d_in[0];
    const float* W_in   = (const float*)d_in[1];
    const float* b_in   = (const float*)d_in[2];
    const float* W_gcn  = (const float*)d_in[3];
    const float* b_gcn  = (const float*)d_in[4];
    const float* W_out1 = (const float*)d_in[5];
    const float* b_out1 = (const float*)d_in[6];
    const float* W_out2 = (const float*)d_in[7];
    const float* b_out2 = (const float*)d_in[8];
    float* out = (float*)d_out;

    const int B = in_sizes[0] / (P * DIN);
    const int blocks = (B + NB - 1) / NB;

    cudaFuncSetAttribute(gnn_fused_kernel,
                         cudaFuncAttributeMaxDynamicSharedMemorySize, SMEM_BYTES);
    gnn_fused_kernel<<<blocks, THREADS, SMEM_BYTES>>>(
        x, W_in, b_in, W_gcn, b_gcn, W_out1, b_out1, W_out2, b_out2, out, B);
}

// round 6
// speedup vs baseline: 1.8130x; 1.1056x over previous
#include <cuda_runtime.h>
#include <cuda_bf16.h>
#include <cstdint>

#define P 12
#define H 128
#define DIN 32
#define NB 16
#define NROWS (NB*P)          // 192
#define THREADS 256
#define STRIDE 272            // bytes per operand-tile row (128 bf16 + 8 pad) -> conflict-free frags

// ---------------- SMEM byte offsets ----------------
#define OFF_BH 0                              // h tile hi bf16 [192][STRIDE]
#define OFF_BL (OFF_BH + NROWS*STRIDE)        // 52224: h tile lo
#define OFF_WH (OFF_BL + NROWS*STRIDE)        // 104448: W^T hi [128][STRIDE]
#define OFF_WL (OFF_WH + H*STRIDE)            // 139264: W^T lo
#define OFF_AHAT (OFF_WL + H*STRIDE)          // 174080: fp32 [NB][12][12]
#define OFF_LON (OFF_AHAT + NB*144*4)         // 183296
#define OFF_DD  (OFF_LON + NROWS*4)           // 184064
#define OFF_G   (OFF_DD + NROWS*4)            // 184832: fp32 [NB][H]
#define OFF_O1  (OFF_G + NB*H*4)              // 193024: fp32 [NB][64]
#define SMEM_BYTES (OFF_O1 + NB*64*4)         // 197120

typedef unsigned long long ull;
typedef uint32_t u32;

__device__ __forceinline__ void ffma2(ull& d, ull a, ull b) {
    asm volatile("fma.rn.f32x2 %0, %1, %2, %0;" : "+l"(d) : "l"(a), "l"(b));
}
__device__ __forceinline__ ull pack2f(float x, float y) {
    ull r; asm("mov.b64 %0, {%1, %2};" : "=l"(r) : "f"(x), "f"(y)); return r;
}
__device__ __forceinline__ float2 unpack2(ull v) {
    float2 f; asm("mov.b64 {%0, %1}, %2;" : "=f"(f.x), "=f"(f.y) : "l"(v)); return f;
}
__device__ __forceinline__ void mma16816(float c[4], const u32 a[4], const u32 b[2]) {
    asm volatile("mma.sync.aligned.m16n8k16.row.col.f32.bf16.bf16.f32 "
                 "{%0,%1,%2,%3}, {%4,%5,%6,%7}, {%8,%9}, {%0,%1,%2,%3};"
                 : "+f"(c[0]), "+f"(c[1]), "+f"(c[2]), "+f"(c[3])
                 : "r"(a[0]), "r"(a[1]), "r"(a[2]), "r"(a[3]), "r"(b[0]), "r"(b[1]));
}
__device__ __forceinline__ u32 packbf(__nv_bfloat16 a, __nv_bfloat16 b) {
    return (u32)__bfloat16_as_ushort(a) | ((u32)__bfloat16_as_ushort(b) << 16);
}

extern __shared__ char smem[];

__device__ __forceinline__ void stHL_W(u32 byte, float v) {
    __nv_bfloat16 hi = __float2bfloat16(v);
    *(__nv_bfloat16*)(smem + OFF_WH + byte) = hi;
    *(__nv_bfloat16*)(smem + OFF_WL + byte) = __float2bfloat16(v - __bfloat162float(hi));
}
__device__ __forceinline__ void stHL_B(u32 byte, float v) {
    __nv_bfloat16 hi = __float2bfloat16(v);
    *(__nv_bfloat16*)(smem + OFF_BH + byte) = hi;
    *(__nv_bfloat16*)(smem + OFF_BL + byte) = __float2bfloat16(v - __bfloat162float(hi));
}

__global__ __launch_bounds__(THREADS, 1)
void gnn_hmma_kernel(const float* __restrict__ x,
                     const float* __restrict__ W_in,
                     const float* __restrict__ b_in,
                     const float* __restrict__ W_gcn,
                     const float* __restrict__ b_gcn,
                     const float* __restrict__ W_out1,
                     const float* __restrict__ b_out1,
                     const float* __restrict__ W_out2,
                     const float* __restrict__ b_out2,
                     float* __restrict__ out,
                     int B)
{
    const int tid  = threadIdx.x;
    const int wid  = tid >> 5, lane = tid & 31;
    const int quad = lane >> 2, tq = lane & 3;
    const int n0   = wid * 16;                 // this warp's n-slice
    const long b0  = (long)blockIdx.x * NB;
    const int  nb  = (B - b0 < NB) ? (int)(B - b0) : NB;

    float* lonF = (float*)(smem + OFF_LON);
    float* dF   = (float*)(smem + OFF_DD);
    float* ahat = (float*)(smem + OFF_AHAT);

    // ---------------- stage x into h tile (hi/lo), save longitudes ----------------
    for (int i = tid; i < NROWS * DIN; i += THREADS) {
        const int r = i >> 5, k = i & 31;
        const float v = (r < nb * P) ? x[b0 * (P * DIN) + i] : 0.f;
        stHL_B((u32)r * STRIDE + (u32)k * 2, v);
        if (k == 0 && r < nb * P) lonF[r] = v;
    }
    __syncthreads();

    // ---------------- adjacency ----------------
    float arow[P];
    if (tid < nb * P) {
        const int g = tid / P;
        const float lp = lonF[tid];
        float deg = 0.f;
        #pragma unroll
        for (int q = 0; q < P; q++) {
            const float lq = lonF[g * P + q];
            float d = fmodf(fabsf(lp - lq), 360.0f);
            float dist = fminf(d, 360.0f - d);
            float a = (dist < 10.0f) ? 1.0f : 0.0f;
            if (q == (tid - g * P)) a += 1.0f;
            arow[q] = a; deg += a;
        }
        dF[tid] = rsqrtf(fmaxf(deg, 1e-12f));
    }
    __syncthreads();
    if (tid < nb * P) {
        const int g = tid / P, p = tid - g * P;
        const float dp = dF[tid];
        #pragma unroll
        for (int q = 0; q < P; q++)
            ahat[(g * P + p) * P + q] = arow[q] * dp * dF[g * P + q];
    }
    // (first ahat use is round-1 mix; multiple barriers in between)

    float c[12][2][4];

    // ---------------- 4 rounds: input proj + 3 GCN layers ----------------
    #pragma unroll 1
    for (int round = 0; round < 4; round++) {
        // stage W^T (hi/lo): Wt[j][k] = W[k][j]
        if (round == 0) {
            for (int i = tid; i < DIN * H; i += THREADS) {
                const int k = i >> 7, j = i & 127;
                stHL_W((u32)j * STRIDE + (u32)k * 2, W_in[i]);
            }
        } else {
            const float* Wg = W_gcn + (round - 1) * H * H;
            for (int i = tid; i < H * H; i += THREADS) {
                const int k = i >> 7, j = i & 127;
                stHL_W((u32)j * STRIDE + (u32)k * 2, Wg[i]);
            }
        }
        __syncthreads();

        #pragma unroll
        for (int t = 0; t < 12; t++)
            #pragma unroll
            for (int nn = 0; nn < 2; nn++) {
                c[t][nn][0] = 0.f; c[t][nn][1] = 0.f; c[t][nn][2] = 0.f; c[t][nn][3] = 0.f;
            }

        const int kmax = (round == 0) ? 2 : 8;
        #pragma unroll 1
        for (int kt = 0; kt < kmax; kt++) {
            const u32 koff = (u32)kt * 32 + (u32)tq * 4;
            u32 bh[2][2], bl[2][2];
            #pragma unroll
            for (int nn = 0; nn < 2; nn++) {
                const u32 jb = (u32)(n0 + 8 * nn + quad) * STRIDE + koff;
                bh[nn][0] = *(const u32*)(smem + OFF_WH + jb);
                bh[nn][1] = *(const u32*)(smem + OFF_WH + jb + 16);
                bl[nn][0] = *(const u32*)(smem + OFF_WL + jb);
                bl[nn][1] = *(const u32*)(smem + OFF_WL + jb + 16);
            }
            #pragma unroll
            for (int t = 0; t < 12; t++) {
                const u32 ra = (u32)(16 * t + quad) * STRIDE + koff;
                u32 ah[4], al[4];
                ah[0] = *(const u32*)(smem + OFF_BH + ra);
                ah[1] = *(const u32*)(smem + OFF_BH + ra + 8 * STRIDE);
                ah[2] = *(const u32*)(smem + OFF_BH + ra + 16);
                ah[3] = *(const u32*)(smem + OFF_BH + ra + 8 * STRIDE + 16);
                al[0] = *(const u32*)(smem + OFF_BL + ra);
                al[1] = *(const u32*)(smem + OFF_BL + ra + 8 * STRIDE);
                al[2] = *(const u32*)(smem + OFF_BL + ra + 16);
                al[3] = *(const u32*)(smem + OFF_BL + ra + 8 * STRIDE + 16);
                #pragma unroll
                for (int nn = 0; nn < 2; nn++) {
                    mma16816(c[t][nn], ah, bh[nn]);   // hi*hi
                    mma16816(c[t][nn], ah, bl[nn]);   // hi*lo
                    mma16816(c[t][nn], al, bh[nn]);   // lo*hi
                }
            }
        }
        __syncthreads();                    // all warps done reading h tile

        // ---- store accumulators as split-bf16 z back into h tile (round 0: +bias) ----
        #pragma unroll
        for (int nn = 0; nn < 2; nn++) {
            const int j0 = n0 + 8 * nn + 2 * tq;
            float badd0 = 0.f, badd1 = 0.f;
            if (round == 0) { badd0 = b_in[j0]; badd1 = b_in[j0 + 1]; }
            #pragma unroll
            for (int t = 0; t < 12; t++) {
                const float v0 = c[t][nn][0] + badd0, v1 = c[t][nn][1] + badd1;
                const float v2 = c[t][nn][2] + badd0, v3 = c[t][nn][3] + badd1;
                const u32 rb = (u32)(16 * t + quad) * STRIDE + (u32)j0 * 2;
                const __nv_bfloat16 h0 = __float2bfloat16(v0), h1 = __float2bfloat16(v1);
                const __nv_bfloat16 h2 = __float2bfloat16(v2), h3 = __float2bfloat16(v3);
                *(u32*)(smem + OFF_BH + rb)              = packbf(h0, h1);
                *(u32*)(smem + OFF_BH + rb + 8 * STRIDE) = packbf(h2, h3);
                *(u32*)(smem + OFF_BL + rb) =
                    packbf(__float2bfloat16(v0 - __bfloat162float(h0)),
                           __float2bfloat16(v1 - __bfloat162float(h1)));
                *(u32*)(smem + OFF_BL + rb + 8 * STRIDE) =
                    packbf(__float2bfloat16(v2 - __bfloat162float(h2)),
                           __float2bfloat16(v3 - __bfloat162float(h3)));
            }
        }
        __syncthreads();

        // ---- mix pass: h = relu(Ahat @ z + b), in place; round 3 pools ----
        if (round >= 1) {
            const int jm = tid & 127;
            const int gb = tid >> 7;
            const float bg = b_gcn[(round - 1) * H + jm];
            #pragma unroll 1
            for (int gi = 0; gi < 8; gi++) {
                const int g = gb * 8 + gi;
                if (g < nb) {
                    const u32 base = (u32)(g * P) * STRIDE + (u32)jm * 2;
                    float z[P];
                    #pragma unroll
                    for (int p = 0; p < P; p++) {
                        const float hiv = __bfloat162float(*(const __nv_bfloat16*)(smem + OFF_BH + base + p * STRIDE));
                        const float lov = __bfloat162float(*(const __nv_bfloat16*)(smem + OFF_BL + base + p * STRIDE));
                        z[p] = hiv + lov;
                    }
                    ull zq[6];
                    #pragma unroll
                    for (int i2 = 0; i2 < 6; i2++) zq[i2] = pack2f(z[2 * i2], z[2 * i2 + 1]);
                    const float* Ag = ahat + g * 144;
                    float pool = 0.f;
                    #pragma unroll
                    for (int p = 0; p < P; p++) {
                        const ulonglong2* ap = (const ulonglong2*)(Ag + p * 12);
                        const ulonglong2 u0 = ap[0], u1 = ap[1], u2 = ap[2];
                        ull o2 = 0ull;
                        ffma2(o2, u0.x, zq[0]); ffma2(o2, u0.y, zq[1]);
                        ffma2(o2, u1.x, zq[2]); ffma2(o2, u1.y, zq[3]);
                        ffma2(o2, u2.x, zq[4]); ffma2(o2, u2.y, zq[5]);
                        const float2 ov = unpack2(o2);
                        const float o = fmaxf(ov.x + ov.y + bg, 0.f);
                        if (round < 3) {
                            const __nv_bfloat16 hh = __float2bfloat16(o);
                            *(__nv_bfloat16*)(smem + OFF_BH + base + p * STRIDE) = hh;
                            *(__nv_bfloat16*)(smem + OFF_BL + base + p * STRIDE) =
                                __float2bfloat16(o - __bfloat162float(hh));
                        } else {
                            pool += o;
                        }
                    }
                    if (round == 3)
                        ((float*)(smem + OFF_G))[g * H + jm] = pool * (1.0f / 12.0f);
                }
            }
        }
        __syncthreads();
    }

    // ---------------- head: g -> relu(g@W1+b1) -> @W2+b2 ----------------
    float* wv  = (float*)(smem + OFF_WH);      // reuse W^T region: [128][64] fp32
    float* sG  = (float*)(smem + OFF_G);
    float* sO1 = (float*)(smem + OFF_O1);
    for (int i = tid; i < H * 64; i += THREADS) wv[i] = W_out1[i];
    __syncthreads();
    for (int i = tid; i < nb * 64; i += THREADS) {
        const int bb = i >> 6, m = i & 63;
        float s = b_out1[m];
        const float* gr = sG + bb * H;
        #pragma unroll 8
        for (int k = 0; k < H; k++) s = fmaf(gr[k], wv[k * 64 + m], s);
        sO1[i] = fmaxf(s, 0.f);
    }
    __syncthreads();
    if (tid < nb * 3) {
        const int bb = tid / 3, d = tid - bb * 3;
        float s = b_out2[d];
        const float* o1 = sO1 + bb * 64;
        #pragma unroll
        for (int m = 0; m < 64; m++) s = fmaf(o1[m], W_out2[m * 3 + d], s);
        out[(b0 + bb) * 3 + d] = s;
    }
}

extern "C" void kernel_launch(void* const* d_in, const int* in_sizes, int n_in,
                              void* d_out, int out_size)
{
    const float* x      = (const float*)d_in[0];
    const float* W_in   = (const float*)d_in[1];
    const float* b_in   = (const float*)d_in[2];
    const float* W_gcn  = (const float*)d_in[3];
    const float* b_gcn  = (const float*)d_in[4];
    const float* W_out1 = (const float*)d_in[5];
    const float* b_out1 = (const float*)d_in[6];
    const float* W_out2 = (const float*)d_in[7];
    const float* b_out2 = (const float*)d_in[8];
    float* out = (float*)d_out;

    const int B = in_sizes[0] / (P * DIN);
    const int blocks = (B + NB - 1) / NB;

    cudaFuncSetAttribute(gnn_hmma_kernel,
                         cudaFuncAttributeMaxDynamicSharedMemorySize, SMEM_BYTES);
    gnn_hmma_kernel<<<blocks, THREADS, SMEM_BYTES>>>(
        x, W_in, b_in, W_gcn, b_gcn, W_out1, b_out1, W_out2, b_out2, out, B);
}

// round 7
// speedup vs baseline: 2.0197x; 1.1140x over previous
#include <cuda_runtime.h>
#include <cuda_bf16.h>
#include <cstdint>

#define P 12
#define H 128
#define DIN 32
#define NB 16
#define NROWS (NB*P)          // 192
#define THREADS 512
#define STRIDE 272            // bytes/row: 128 bf16 + 8 pad -> conflict-free LDSM

// ---------------- SMEM byte offsets ----------------
#define OFF_BH 0                              // h tile hi bf16 [192][STRIDE]
#define OFF_BL (OFF_BH + NROWS*STRIDE)        // 52224
#define OFF_WH (OFF_BL + NROWS*STRIDE)        // 104448: W^T hi [128][STRIDE]
#define OFF_WL (OFF_WH + H*STRIDE)            // 139264
#define OFF_AHAT (OFF_WL + H*STRIDE)          // 174080: fp32 [NB][12][12]
#define OFF_LON (OFF_AHAT + NB*144*4)         // 183296
#define OFF_DD  (OFF_LON + NROWS*4)           // 184064
#define OFF_G   (OFF_DD + NROWS*4)            // 184832: fp32 [NB][H]
#define OFF_O1  (OFF_G + NB*H*4)              // 193024: fp32 [NB][64]
#define SMEM_BYTES (OFF_O1 + NB*64*4)         // 197120

typedef unsigned long long ull;
typedef uint32_t u32;

__device__ __forceinline__ void ffma2(ull& d, ull a, ull b) {
    asm volatile("fma.rn.f32x2 %0, %1, %2, %0;" : "+l"(d) : "l"(a), "l"(b));
}
__device__ __forceinline__ ull pack2f(float x, float y) {
    ull r; asm("mov.b64 %0, {%1, %2};" : "=l"(r) : "f"(x), "f"(y)); return r;
}
__device__ __forceinline__ float2 unpack2(ull v) {
    float2 f; asm("mov.b64 {%0, %1}, %2;" : "=f"(f.x), "=f"(f.y) : "l"(v)); return f;
}
__device__ __forceinline__ void mma16816(float c[4], const u32 a[4], u32 b0, u32 b1) {
    asm volatile("mma.sync.aligned.m16n8k16.row.col.f32.bf16.bf16.f32 "
                 "{%0,%1,%2,%3}, {%4,%5,%6,%7}, {%8,%9}, {%0,%1,%2,%3};"
                 : "+f"(c[0]), "+f"(c[1]), "+f"(c[2]), "+f"(c[3])
                 : "r"(a[0]), "r"(a[1]), "r"(a[2]), "r"(a[3]), "r"(b0), "r"(b1));
}
__device__ __forceinline__ void ldsm4(u32 r[4], u32 addr) {
    asm volatile("ldmatrix.sync.aligned.m8n8.x4.shared.b16 {%0,%1,%2,%3}, [%4];"
        : "=r"(r[0]), "=r"(r[1]), "=r"(r[2]), "=r"(r[3]) : "r"(addr));
}
__device__ __forceinline__ u32 packbf(__nv_bfloat16 a, __nv_bfloat16 b) {
    return (u32)__bfloat16_as_ushort(a) | ((u32)__bfloat16_as_ushort(b) << 16);
}
__device__ __forceinline__ u32 smem_u32(const void* p) {
    u32 a;
    asm("{ .reg .u64 t; cvta.to.shared.u64 t, %1; cvt.u32.u64 %0, t; }" : "=r"(a) : "l"(p));
    return a;
}

extern __shared__ char smem[];

__device__ __forceinline__ void stHL_W(u32 byte, float v) {
    __nv_bfloat16 hi = __float2bfloat16(v);
    *(__nv_bfloat16*)(smem + OFF_WH + byte) = hi;
    *(__nv_bfloat16*)(smem + OFF_WL + byte) = __float2bfloat16(v - __bfloat162float(hi));
}
__device__ __forceinline__ void stHL_B(u32 byte, float v) {
    __nv_bfloat16 hi = __float2bfloat16(v);
    *(__nv_bfloat16*)(smem + OFF_BH + byte) = hi;
    *(__nv_bfloat16*)(smem + OFF_BL + byte) = __float2bfloat16(v - __bfloat162float(hi));
}

__global__ __launch_bounds__(THREADS, 1)
void gnn_hmma2_kernel(const float* __restrict__ x,
                      const float* __restrict__ W_in,
                      const float* __restrict__ b_in,
                      const float* __restrict__ W_gcn,
                      const float* __restrict__ b_gcn,
                      const float* __restrict__ W_out1,
                      const float* __restrict__ b_out1,
                      const float* __restrict__ W_out2,
                      const float* __restrict__ b_out2,
                      float* __restrict__ out,
                      int B)
{
    const int tid  = threadIdx.x;
    const int wid  = tid >> 5, lane = tid & 31;
    const int quad = lane >> 2, tq = lane & 3;
    const int mg   = wid >> 2;               // m-group 0..3: tiles {mg, mg+4, mg+8}
    const int ng   = wid & 3;                // n-group 0..3: cols [32ng, 32ng+32)
    const long b0  = (long)blockIdx.x * NB;
    const int  nb  = (B - b0 < NB) ? (int)(B - b0) : NB;

    const u32 sbase = smem_u32(smem);
    // lane-invariant parts of LDSM addresses
    const u32 a_lane = (u32)((lane & 7) + 8 * ((lane >> 3) & 1)) * STRIDE + (u32)(lane >> 4) * 16;
    const u32 b_lane = (u32)(32 * ng + lane) * STRIDE;

    float* lonF = (float*)(smem + OFF_LON);
    float* dF   = (float*)(smem + OFF_DD);
    float* ahat = (float*)(smem + OFF_AHAT);

    // ---------------- stage x into h tile (hi/lo), save longitudes ----------------
    for (int i = tid; i < NROWS * DIN; i += THREADS) {
        const int r = i >> 5, k = i & 31;
        const float v = (r < nb * P) ? x[b0 * (P * DIN) + i] : 0.f;
        stHL_B((u32)r * STRIDE + (u32)k * 2, v);
        if (k == 0 && r < nb * P) lonF[r] = v;
    }
    __syncthreads();

    // ---------------- adjacency ----------------
    float arow[P];
    if (tid < nb * P) {
        const int g = tid / P;
        const float lp = lonF[tid];
        float deg = 0.f;
        #pragma unroll
        for (int q = 0; q < P; q++) {
            const float lq = lonF[g * P + q];
            float d = fmodf(fabsf(lp - lq), 360.0f);
            float dist = fminf(d, 360.0f - d);
            float a = (dist < 10.0f) ? 1.0f : 0.0f;
            if (q == (tid - g * P)) a += 1.0f;
            arow[q] = a; deg += a;
        }
        dF[tid] = rsqrtf(fmaxf(deg, 1e-12f));
    }
    __syncthreads();
    if (tid < nb * P) {
        const int g = tid / P, p = tid - g * P;
        const float dp = dF[tid];
        #pragma unroll
        for (int q = 0; q < P; q++)
            ahat[(g * P + p) * P + q] = arow[q] * dp * dF[g * P + q];
    }

    float c[3][4][4];

    // ---------------- 4 rounds: input proj + 3 GCN layers ----------------
    #pragma unroll 1
    for (int round = 0; round < 4; round++) {
        // ---- stage W^T (hi/lo): Wt[j][k] = W[k][j] ----
        if (round == 0) {
            for (int i = tid; i < DIN * H; i += THREADS) {
                const int k = i >> 7, j = i & 127;
                stHL_W((u32)j * STRIDE + (u32)k * 2, W_in[i]);
            }
        } else {
            const float* Wg = W_gcn + (round - 1) * H * H;
            for (int i = tid; i < H * H; i += THREADS) {
                const int k = i >> 7, j = i & 127;
                stHL_W((u32)j * STRIDE + (u32)k * 2, Wg[i]);
            }
        }
        __syncthreads();   // W staged + prev round's mix writes to B visible

        #pragma unroll
        for (int tl = 0; tl < 3; tl++)
            #pragma unroll
            for (int f = 0; f < 4; f++) {
                c[tl][f][0] = 0.f; c[tl][f][1] = 0.f; c[tl][f][2] = 0.f; c[tl][f][3] = 0.f;
            }

        const int kmax = (round == 0) ? 2 : 8;
        #pragma unroll 1
        for (int kt = 0; kt < kmax; kt++) {
            const u32 kb = (u32)kt * 32;
            // B fragments: hi/lo, k-low (b0 of 4 frags) + k-high (b1 of 4 frags)
            u32 bh0[4], bh1[4], bl0[4], bl1[4];
            ldsm4(bh0, sbase + OFF_WH + b_lane + kb);
            ldsm4(bh1, sbase + OFF_WH + b_lane + kb + 16);
            ldsm4(bl0, sbase + OFF_WL + b_lane + kb);
            ldsm4(bl1, sbase + OFF_WL + b_lane + kb + 16);
            #pragma unroll
            for (int tl = 0; tl < 3; tl++) {
                const u32 rbase = (u32)(16 * (mg + 4 * tl)) * STRIDE + a_lane + kb;
                u32 ah[4], al[4];
                ldsm4(ah, sbase + OFF_BH + rbase);
                ldsm4(al, sbase + OFF_BL + rbase);
                #pragma unroll
                for (int f = 0; f < 4; f++) {
                    mma16816(c[tl][f], ah, bh0[f], bh1[f]);  // hi*hi
                    mma16816(c[tl][f], ah, bl0[f], bl1[f]);  // hi*lo
                    mma16816(c[tl][f], al, bh0[f], bh1[f]);  // lo*hi
                }
            }
        }
        __syncthreads();   // all warps done reading h tile

        // ---- epilogue: split-bf16 z into h tile (round 0: +bias) ----
        #pragma unroll
        for (int f = 0; f < 4; f++) {
            const int j0 = 32 * ng + 8 * f + 2 * tq;
            float badd0 = 0.f, badd1 = 0.f;
            if (round == 0) { badd0 = b_in[j0]; badd1 = b_in[j0 + 1]; }
            #pragma unroll
            for (int tl = 0; tl < 3; tl++) {
                const int t = mg + 4 * tl;
                const float v0 = c[tl][f][0] + badd0, v1 = c[tl][f][1] + badd1;
                const float v2 = c[tl][f][2] + badd0, v3 = c[tl][f][3] + badd1;
                const u32 rb = (u32)(16 * t + quad) * STRIDE + (u32)j0 * 2;
                const __nv_bfloat16 h0 = __float2bfloat16(v0), h1 = __float2bfloat16(v1);
                const __nv_bfloat16 h2 = __float2bfloat16(v2), h3 = __float2bfloat16(v3);
                *(u32*)(smem + OFF_BH + rb)              = packbf(h0, h1);
                *(u32*)(smem + OFF_BH + rb + 8 * STRIDE) = packbf(h2, h3);
                *(u32*)(smem + OFF_BL + rb) =
                    packbf(__float2bfloat16(v0 - __bfloat162float(h0)),
                           __float2bfloat16(v1 - __bfloat162float(h1)));
                *(u32*)(smem + OFF_BL + rb + 8 * STRIDE) =
                    packbf(__float2bfloat16(v2 - __bfloat162float(h2)),
                           __float2bfloat16(v3 - __bfloat162float(h3)));
            }
        }
        __syncthreads();

        // ---- mix pass: h = relu(Ahat @ z + b), in place; round 3 pools ----
        if (round >= 1) {
            const int jm = tid & 127;
            const int gb = tid >> 7;               // 0..3
            const float bg = b_gcn[(round - 1) * H + jm];
            #pragma unroll 1
            for (int gi = 0; gi < 4; gi++) {
                const int g = gb * 4 + gi;
                if (g < nb) {
                    const u32 base = (u32)(g * P) * STRIDE + (u32)jm * 2;
                    float z[P];
                    #pragma unroll
                    for (int p = 0; p < P; p++) {
                        const float hiv = __bfloat162float(*(const __nv_bfloat16*)(smem + OFF_BH + base + p * STRIDE));
                        const float lov = __bfloat162float(*(const __nv_bfloat16*)(smem + OFF_BL + base + p * STRIDE));
                        z[p] = hiv + lov;
                    }
                    ull zq[6];
                    #pragma unroll
                    for (int i2 = 0; i2 < 6; i2++) zq[i2] = pack2f(z[2 * i2], z[2 * i2 + 1]);
                    const float* Ag = ahat + g * 144;
                    float pool = 0.f;
                    #pragma unroll
                    for (int p = 0; p < P; p++) {
                        const ulonglong2* ap = (const ulonglong2*)(Ag + p * 12);
                        const ulonglong2 u0 = ap[0], u1 = ap[1], u2 = ap[2];
                        ull o2 = 0ull;
                        ffma2(o2, u0.x, zq[0]); ffma2(o2, u0.y, zq[1]);
                        ffma2(o2, u1.x, zq[2]); ffma2(o2, u1.y, zq[3]);
                        ffma2(o2, u2.x, zq[4]); ffma2(o2, u2.y, zq[5]);
                        const float2 ov = unpack2(o2);
                        const float o = fmaxf(ov.x + ov.y + bg, 0.f);
                        if (round < 3) {
                            const __nv_bfloat16 hh = __float2bfloat16(o);
                            *(__nv_bfloat16*)(smem + OFF_BH + base + p * STRIDE) = hh;
                            *(__nv_bfloat16*)(smem + OFF_BL + base + p * STRIDE) =
                                __float2bfloat16(o - __bfloat162float(hh));
                        } else {
                            pool += o;
                        }
                    }
                    if (round == 3)
                        ((float*)(smem + OFF_G))[g * H + jm] = pool * (1.0f / 12.0f);
                }
            }
        }
        __syncthreads();
    }

    // ---------------- head: g -> relu(g@W1+b1) -> @W2+b2 ----------------
    float* wv  = (float*)(smem + OFF_WH);      // reuse W^T region: [128][64] fp32
    float* sG  = (float*)(smem + OFF_G);
    float* sO1 = (float*)(smem + OFF_O1);
    for (int i = tid; i < H * 64; i += THREADS) wv[i] = W_out1[i];
    __syncthreads();
    for (int i = tid; i < nb * 64; i += THREADS) {
        const int bb = i >> 6, m = i & 63;
        float s = b_out1[m];
        const float* gr = sG + bb * H;
        #pragma unroll 8
        for (int k = 0; k < H; k++) s = fmaf(gr[k], wv[k * 64 + m], s);
        sO1[i] = fmaxf(s, 0.f);
    }
    __syncthreads();
    if (tid < nb * 3) {
        const int bb = tid / 3, d = tid - bb * 3;
        float s = b_out2[d];
        const float* o1 = sO1 + bb * 64;
        #pragma unroll
        for (int m = 0; m < 64; m++) s = fmaf(o1[m], W_out2[m * 3 + d], s);
        out[(b0 + bb) * 3 + d] = s;
    }
}

extern "C" void kernel_launch(void* const* d_in, const int* in_sizes, int n_in,
                              void* d_out, int out_size)
{
    const float* x      = (const float*)d_in[0];
    const float* W_in   = (const float*)d_in[1];
    const float* b_in   = (const float*)d_in[2];
    const float* W_gcn  = (const float*)d_in[3];
    const float* b_gcn  = (const float*)d_in[4];
    const float* W_out1 = (const float*)d_in[5];
    const float* b_out1 = (const float*)d_in[6];
    const float* W_out2 = (const float*)d_in[7];
    const float* b_out2 = (const float*)d_in[8];
    float* out = (float*)d_out;

    const int B = in_sizes[0] / (P * DIN);
    const int blocks = (B + NB - 1) / NB;

    cudaFuncSetAttribute(gnn_hmma2_kernel,
                         cudaFuncAttributeMaxDynamicSharedMemorySize, SMEM_BYTES);
    gnn_hmma2_kernel<<<blocks, THREADS, SMEM_BYTES>>>(
        x, W_in, b_in, W_gcn, b_gcn, W_out1, b_out1, W_out2, b_out2, out, B);
}

// round 8
// speedup vs baseline: 3.0911x; 1.5304x over previous
#include <cuda_runtime.h>
#include <cuda_bf16.h>
#include <cstdint>

#define P 12
#define H 128
#define DIN 32
#define NB 8
#define NROWSB (NB*P)         // 96 rows, 6 m-tiles
#define THREADS 384
#define STRIDE 272            // bytes/row: 128 bf16 + 8 pad -> conflict-free LDSM

// ---------------- SMEM byte offsets ----------------
#define OFF_BH 0                              // h tile hi bf16 [96][STRIDE]
#define OFF_BL (OFF_BH + NROWSB*STRIDE)       // 26112
#define OFF_AHAT (OFF_BL + NROWSB*STRIDE)     // 52224: fp32 [NB][12][12]
#define OFF_LON (OFF_AHAT + NB*144*4)         // 56832
#define OFF_DD  (OFF_LON + NROWSB*4)          // 57216
#define OFF_G   (OFF_DD + NROWSB*4)           // 57600: fp32 [NB][H]
#define OFF_O1  (OFF_G + NB*H*4)              // 61696: fp32 [NB][64]
#define SMEM_BYTES (OFF_O1 + NB*64*4)         // 63744

typedef unsigned long long ull;
typedef uint32_t u32;

// W fragment buffer: [l(4)][kt(8)][jf(16)][lane(32)] x uint4 {b0h,b1h,b0l,b1l}
__device__ __align__(16) unsigned char g_wbuf[4 * 8 * 16 * 32 * 16];

__device__ __forceinline__ void ffma2(ull& d, ull a, ull b) {
    asm volatile("fma.rn.f32x2 %0, %1, %2, %0;" : "+l"(d) : "l"(a), "l"(b));
}
__device__ __forceinline__ ull pack2f(float x, float y) {
    ull r; asm("mov.b64 %0, {%1, %2};" : "=l"(r) : "f"(x), "f"(y)); return r;
}
__device__ __forceinline__ float2 unpack2(ull v) {
    float2 f; asm("mov.b64 {%0, %1}, %2;" : "=f"(f.x), "=f"(f.y) : "l"(v)); return f;
}
__device__ __forceinline__ void mma16816(float c[4], const u32 a[4], u32 b0, u32 b1) {
    asm volatile("mma.sync.aligned.m16n8k16.row.col.f32.bf16.bf16.f32 "
                 "{%0,%1,%2,%3}, {%4,%5,%6,%7}, {%8,%9}, {%0,%1,%2,%3};"
                 : "+f"(c[0]), "+f"(c[1]), "+f"(c[2]), "+f"(c[3])
                 : "r"(a[0]), "r"(a[1]), "r"(a[2]), "r"(a[3]), "r"(b0), "r"(b1));
}
__device__ __forceinline__ void ldsm4(u32 r[4], u32 addr) {
    asm volatile("ldmatrix.sync.aligned.m8n8.x4.shared.b16 {%0,%1,%2,%3}, [%4];"
        : "=r"(r[0]), "=r"(r[1]), "=r"(r[2]), "=r"(r[3]) : "r"(addr));
}
__device__ __forceinline__ u32 packbf(__nv_bfloat16 a, __nv_bfloat16 b) {
    return (u32)__bfloat16_as_ushort(a) | ((u32)__bfloat16_as_ushort(b) << 16);
}
__device__ __forceinline__ u32 smem_u32(const void* p) {
    u32 a;
    asm("{ .reg .u64 t; cvta.to.shared.u64 t, %1; cvt.u32.u64 %0, t; }" : "=r"(a) : "l"(p));
    return a;
}

// ---------------- pre-kernel: fp32 W -> split-bf16 mma fragments ----------------
__global__ void conv_w_kernel(const float* __restrict__ W_in,
                              const float* __restrict__ W_gcn)
{
    const int idx = blockIdx.x * 256 + threadIdx.x;   // 16384 total
    const int lane = idx & 31;
    const int jf   = (idx >> 5) & 15;
    const int kt   = (idx >> 9) & 7;
    const int l    = idx >> 12;
    if (l == 0 && kt >= 2) return;                    // input proj has K=32 only
    const int quad = lane >> 2, tq = lane & 3;
    const int j  = 8 * jf + quad;
    const int k0 = 16 * kt + 2 * tq;
    const float* W = (l == 0) ? W_in : (W_gcn + (l - 1) * H * H);
    const float w00 = W[k0 * H + j],       w01 = W[(k0 + 1) * H + j];
    const float w10 = W[(k0 + 8) * H + j], w11 = W[(k0 + 9) * H + j];
    const __nv_bfloat16 h00 = __float2bfloat16(w00), h01 = __float2bfloat16(w01);
    const __nv_bfloat16 h10 = __float2bfloat16(w10), h11 = __float2bfloat16(w11);
    uint4 v;
    v.x = packbf(h00, h01);
    v.y = packbf(h10, h11);
    v.z = packbf(__float2bfloat16(w00 - __bfloat162float(h00)),
                 __float2bfloat16(w01 - __bfloat162float(h01)));
    v.w = packbf(__float2bfloat16(w10 - __bfloat162float(h10)),
                 __float2bfloat16(w11 - __bfloat162float(h11)));
    *(uint4*)(g_wbuf + (size_t)((((l * 8 + kt) * 16 + jf) * 32 + lane)) * 16) = v;
}

extern __shared__ char smem[];

__device__ __forceinline__ void stHL_B(u32 byte, float v) {
    __nv_bfloat16 hi = __float2bfloat16(v);
    *(__nv_bfloat16*)(smem + OFF_BH + byte) = hi;
    *(__nv_bfloat16*)(smem + OFF_BL + byte) = __float2bfloat16(v - __bfloat162float(hi));
}

__global__ __launch_bounds__(THREADS, 2)
void gnn_hmma3_kernel(const float* __restrict__ x,
                      const float* __restrict__ b_in,
                      const float* __restrict__ b_gcn,
                      const float* __restrict__ W_out1,
                      const float* __restrict__ b_out1,
                      const float* __restrict__ W_out2,
                      const float* __restrict__ b_out2,
                      float* __restrict__ out,
                      int B)
{
    const int tid  = threadIdx.x;
    const int wid  = tid >> 5, lane = tid & 31;
    const int quad = lane >> 2, tq = lane & 3;
    const int mg   = wid / 4;                // 0..2: m-tiles {mg, mg+3}
    const int ng   = wid & 3;                // 0..3: cols [32ng, 32ng+32)
    const long b0  = (long)blockIdx.x * NB;
    const int  nb  = (B - b0 < NB) ? (int)(B - b0) : NB;

    const u32 sbase = smem_u32(smem);
    const u32 a_lane = (u32)((lane & 7) + 8 * ((lane >> 3) & 1)) * STRIDE + (u32)(lane >> 4) * 16;

    float* lonF = (float*)(smem + OFF_LON);
    float* dF   = (float*)(smem + OFF_DD);
    float* ahat = (float*)(smem + OFF_AHAT);

    // ---------------- stage x into h tile (hi/lo), save longitudes ----------------
    for (int i = tid; i < NROWSB * DIN; i += THREADS) {
        const int r = i >> 5, k = i & 31;
        const float v = (r < nb * P) ? x[b0 * (P * DIN) + i] : 0.f;
        stHL_B((u32)r * STRIDE + (u32)k * 2, v);
        if (k == 0 && r < nb * P) lonF[r] = v;
    }
    __syncthreads();

    // ---------------- adjacency ----------------
    float arow[P];
    if (tid < nb * P) {
        const int g = tid / P;
        const float lp = lonF[tid];
        float deg = 0.f;
        #pragma unroll
        for (int q = 0; q < P; q++) {
            const float lq = lonF[g * P + q];
            float d = fmodf(fabsf(lp - lq), 360.0f);
            float dist = fminf(d, 360.0f - d);
            float a = (dist < 10.0f) ? 1.0f : 0.0f;
            if (q == (tid - g * P)) a += 1.0f;
            arow[q] = a; deg += a;
        }
        dF[tid] = rsqrtf(fmaxf(deg, 1e-12f));
    }
    __syncthreads();
    if (tid < nb * P) {
        const int g = tid / P, p = tid - g * P;
        const float dp = dF[tid];
        #pragma unroll
        for (int q = 0; q < P; q++)
            ahat[(g * P + p) * P + q] = arow[q] * dp * dF[g * P + q];
    }

    float c[2][4][4];

    // ---------------- 4 rounds: input proj + 3 GCN layers ----------------
    #pragma unroll 1
    for (int round = 0; round < 4; round++) {
        __syncthreads();   // B-tile writes (staging / prev mix) + ahat visible

        #pragma unroll
        for (int tl = 0; tl < 2; tl++)
            #pragma unroll
            for (int f = 0; f < 4; f++) {
                c[tl][f][0] = 0.f; c[tl][f][1] = 0.f; c[tl][f][2] = 0.f; c[tl][f][3] = 0.f;
            }

        const int kmax = (round == 0) ? 2 : 8;
        const unsigned char* wb = g_wbuf
            + (size_t)(((round * 8) * 16 + 4 * ng) * 32 + lane) * 16;
        #pragma unroll 1
        for (int kt = 0; kt < kmax; kt++) {
            const u32 kb = (u32)kt * 32;
            uint4 wf0 = *(const uint4*)(wb + (size_t)kt * 8192);
            uint4 wf1 = *(const uint4*)(wb + (size_t)kt * 8192 + 512);
            uint4 wf2 = *(const uint4*)(wb + (size_t)kt * 8192 + 1024);
            uint4 wf3 = *(const uint4*)(wb + (size_t)kt * 8192 + 1536);
            #pragma unroll
            for (int tl = 0; tl < 2; tl++) {
                const u32 rbase = (u32)(16 * (mg + 3 * tl)) * STRIDE + a_lane + kb;
                u32 ah[4], al[4];
                ldsm4(ah, sbase + OFF_BH + rbase);
                ldsm4(al, sbase + OFF_BL + rbase);
                mma16816(c[tl][0], ah, wf0.x, wf0.y);
                mma16816(c[tl][0], ah, wf0.z, wf0.w);
                mma16816(c[tl][0], al, wf0.x, wf0.y);
                mma16816(c[tl][1], ah, wf1.x, wf1.y);
                mma16816(c[tl][1], ah, wf1.z, wf1.w);
                mma16816(c[tl][1], al, wf1.x, wf1.y);
                mma16816(c[tl][2], ah, wf2.x, wf2.y);
                mma16816(c[tl][2], ah, wf2.z, wf2.w);
                mma16816(c[tl][2], al, wf2.x, wf2.y);
                mma16816(c[tl][3], ah, wf3.x, wf3.y);
                mma16816(c[tl][3], ah, wf3.z, wf3.w);
                mma16816(c[tl][3], al, wf3.x, wf3.y);
            }
        }
        __syncthreads();   // all warps done reading h tile

        // ---- epilogue: split-bf16 z back into h tile (round 0: +bias) ----
        #pragma unroll
        for (int f = 0; f < 4; f++) {
            const int j0 = 32 * ng + 8 * f + 2 * tq;
            float badd0 = 0.f, badd1 = 0.f;
            if (round == 0) { badd0 = b_in[j0]; badd1 = b_in[j0 + 1]; }
            #pragma unroll
            for (int tl = 0; tl < 2; tl++) {
                const int t = mg + 3 * tl;
                const float v0 = c[tl][f][0] + badd0, v1 = c[tl][f][1] + badd1;
                const float v2 = c[tl][f][2] + badd0, v3 = c[tl][f][3] + badd1;
                const u32 rb = (u32)(16 * t + quad) * STRIDE + (u32)j0 * 2;
                const __nv_bfloat16 h0 = __float2bfloat16(v0), h1 = __float2bfloat16(v1);
                const __nv_bfloat16 h2 = __float2bfloat16(v2), h3 = __float2bfloat16(v3);
                *(u32*)(smem + OFF_BH + rb)              = packbf(h0, h1);
                *(u32*)(smem + OFF_BH + rb + 8 * STRIDE) = packbf(h2, h3);
                *(u32*)(smem + OFF_BL + rb) =
                    packbf(__float2bfloat16(v0 - __bfloat162float(h0)),
                           __float2bfloat16(v1 - __bfloat162float(h1)));
                *(u32*)(smem + OFF_BL + rb + 8 * STRIDE) =
                    packbf(__float2bfloat16(v2 - __bfloat162float(h2)),
                           __float2bfloat16(v3 - __bfloat162float(h3)));
            }
        }
        __syncthreads();

        // ---- mix pass: h = relu(Ahat @ z + b), in place; round 3 pools ----
        if (round >= 1) {
            const int jm = tid & 127;
            const int gb = tid >> 7;               // 0..2
            const float bg = b_gcn[(round - 1) * H + jm];
            #pragma unroll 1
            for (int gi = 0; gi < 3; gi++) {
                const int g = gb + 3 * gi;
                if (g < nb) {
                    const u32 base = (u32)(g * P) * STRIDE + (u32)jm * 2;
                    float z[P];
                    #pragma unroll
                    for (int p = 0; p < P; p++) {
                        const float hiv = __bfloat162float(*(const __nv_bfloat16*)(smem + OFF_BH + base + p * STRIDE));
                        const float lov = __bfloat162float(*(const __nv_bfloat16*)(smem + OFF_BL + base + p * STRIDE));
                        z[p] = hiv + lov;
                    }
                    ull zq[6];
                    #pragma unroll
                    for (int i2 = 0; i2 < 6; i2++) zq[i2] = pack2f(z[2 * i2], z[2 * i2 + 1]);
                    const float* Ag = ahat + g * 144;
                    float pool = 0.f;
                    #pragma unroll
                    for (int p = 0; p < P; p++) {
                        const ulonglong2* ap = (const ulonglong2*)(Ag + p * 12);
                        const ulonglong2 u0 = ap[0], u1 = ap[1], u2 = ap[2];
                        ull o2 = 0ull;
                        ffma2(o2, u0.x, zq[0]); ffma2(o2, u0.y, zq[1]);
                        ffma2(o2, u1.x, zq[2]); ffma2(o2, u1.y, zq[3]);
                        ffma2(o2, u2.x, zq[4]); ffma2(o2, u2.y, zq[5]);
                        const float2 ov = unpack2(o2);
                        const float o = fmaxf(ov.x + ov.y + bg, 0.f);
                        if (round < 3) {
                            const __nv_bfloat16 hh = __float2bfloat16(o);
                            *(__nv_bfloat16*)(smem + OFF_BH + base + p * STRIDE) = hh;
                            *(__nv_bfloat16*)(smem + OFF_BL + base + p * STRIDE) =
                                __float2bfloat16(o - __bfloat162float(hh));
                        } else {
                            pool += o;
                        }
                    }
                    if (round == 3)
                        ((float*)(smem + OFF_G))[g * H + jm] = pool * (1.0f / 12.0f);
                }
            }
        }
    }
    __syncthreads();

    // ---------------- head: g -> relu(g@W1+b1) -> @W2+b2 ----------------
    float* wv  = (float*)(smem + OFF_BH);      // reuse B tile: [128][64] fp32
    float* sG  = (float*)(smem + OFF_G);
    float* sO1 = (float*)(smem + OFF_O1);
    for (int i = tid; i < H * 64; i += THREADS) wv[i] = W_out1[i];
    __syncthreads();
    for (int i = tid; i < nb * 64; i += THREADS) {
        const int bb = i >> 6, m = i & 63;
        float s = b_out1[m];
        const float* gr = sG + bb * H;
        #pragma unroll 8
        for (int k = 0; k < H; k++) s = fmaf(gr[k], wv[k * 64 + m], s);
        sO1[i] = fmaxf(s, 0.f);
    }
    __syncthreads();
    if (tid < nb * 3) {
        const int bb = tid / 3, d = tid - bb * 3;
        float s = b_out2[d];
        const float* o1 = sO1 + bb * 64;
        #pragma unroll
        for (int m = 0; m < 64; m++) s = fmaf(o1[m], W_out2[m * 3 + d], s);
        out[(b0 + bb) * 3 + d] = s;
    }
}

extern "C" void kernel_launch(void* const* d_in, const int* in_sizes, int n_in,
                              void* d_out, int out_size)
{
    const float* x      = (const float*)d_in[0];
    const float* W_in   = (const float*)d_in[1];
    const float* b_in   = (const float*)d_in[2];
    const float* W_gcn  = (const float*)d_in[3];
    const float* b_gcn  = (const float*)d_in[4];
    const float* W_out1 = (const float*)d_in[5];
    const float* b_out1 = (const float*)d_in[6];
    const float* W_out2 = (const float*)d_in[7];
    const float* b_out2 = (const float*)d_in[8];
    float* out = (float*)d_out;

    const int B = in_sizes[0] / (P * DIN);
    const int blocks = (B + NB - 1) / NB;

    conv_w_kernel<<<64, 256>>>(W_in, W_gcn);

    cudaFuncSetAttribute(gnn_hmma3_kernel,
                         cudaFuncAttributeMaxDynamicSharedMemorySize, SMEM_BYTES);
    gnn_hmma3_kernel<<<blocks, THREADS, SMEM_BYTES>>>(
        x, b_in, b_gcn, W_out1, b_out1, W_out2, b_out2, out, B);
}